// round 13
// baseline (speedup 1.0000x reference)
#include <cuda_runtime.h>
#include <cuda_fp16.h>

#define BATCH   128
#define NUM_IN  4096
#define NLEV    8
#define H       32768
#define KFAN    32
#define NOUT    256
#define KOUT    64
#define SCALE   4.9f
#define CHUNK   16                    // nodes per cp.async stage

#define NODES   (NUM_IN + NLEV * H)   // 266240 nodes, node-major

// Node-major activation buffer in fp16: buf[node * BATCH + b].  ~65 MB scratch.
__device__ __align__(256) __half g_buf[(size_t)NODES * BATCH];

__device__ __forceinline__ float fast_sigmoid(float x) {
    return 1.0f / (1.0f + __expf(-x));
}

// ---------------------------------------------------------------------------
// Kernel 1: transpose+quantize x [B, NUM_IN] -> g_buf[n*B + b] (fp16).
// ---------------------------------------------------------------------------
__global__ void init_buf_kernel(const float* __restrict__ x) {
    const int n = blockIdx.x;
    const int b = threadIdx.x;
    g_buf[(size_t)n * BATCH + b] = __float2half_rn(__ldg(&x[(size_t)b * NUM_IN + n]));
}

// FMA a 4-half smem word into the fp32 accumulator quad.
__device__ __forceinline__ void fma4u(const uint2 v, const float wv,
                                      float& x, float& y, float& z, float& w_) {
    const float2 f01 = __half22float2(*(const __half2*)&v.x);
    const float2 f23 = __half22float2(*(const __half2*)&v.y);
    x  = fmaf(wv, f01.x, x);
    y  = fmaf(wv, f01.y, y);
    z  = fmaf(wv, f23.x, z);
    w_ = fmaf(wv, f23.y, w_);
}

// ---------------------------------------------------------------------------
// Kernel 2: one topological level, cp.async-staged gathers.
// One warp per unit; lane owns a batch quad. Gathers land in a per-warp
// smem double buffer via cp.async (8B per lane per node): in-flight data
// costs ZERO registers, so MLP=16/warp at full champion occupancy.
// Each lane consumes exactly the bytes it copied -> wait_group suffices,
// no barriers. Math identical to the R3 champion (fp32 convert + FMA).
// ---------------------------------------------------------------------------
__global__ void __launch_bounds__(128, 7) level_kernel(
    const float* __restrict__ w,    // [H, K] for this level
    const int*   __restrict__ idx,  // [H, K] for this level
    int base)                       // first output node id of this level
{
    // [warp][stage][node_in_chunk][256 bytes]  = 32 KB
    __shared__ __align__(16) unsigned char s_stage[4][2][CHUNK][256];

    const int lane = threadIdx.x & 31;   // batch quad: 4*lane .. 4*lane+3
    const int wid  = threadIdx.x >> 5;
    const int h    = blockIdx.x * 4 + wid;

    const int4*   ip4 = (const int4*)  (idx + (size_t)h * KFAN);
    const float4* wp4 = (const float4*)(w   + (size_t)h * KFAN);
    const char*   gbase = (const char*)g_buf;

    // ---- Prefetch both chunks (32 cp.async in flight per warp) ----
#pragma unroll
    for (int c = 0; c < 2; ++c) {
#pragma unroll
        for (int jj = 0; jj < CHUNK / 4; ++jj) {
            const int4 i4 = __ldg(ip4 + c * (CHUNK / 4) + jj);
            const int j0 = jj * 4;
#pragma unroll
            for (int q = 0; q < 4; ++q) {
                const int n = (q == 0) ? i4.x : (q == 1) ? i4.y : (q == 2) ? i4.z : i4.w;
                const char* src = gbase + (size_t)n * 256 + lane * 8;
                const unsigned dst = (unsigned)__cvta_generic_to_shared(
                    &s_stage[wid][c][j0 + q][lane * 8]);
                asm volatile("cp.async.ca.shared.global [%0], [%1], 8;\n"
                             :: "r"(dst), "l"(src));
            }
        }
        asm volatile("cp.async.commit_group;\n");
    }

    float ax = 0.f, ay = 0.f, az = 0.f, aw = 0.f;

    // ---- Consume chunk 0 (chunk 1 still in flight) ----
    asm volatile("cp.async.wait_group 1;\n");
#pragma unroll
    for (int jj = 0; jj < CHUNK / 4; ++jj) {
        const float4 w4 = __ldg(wp4 + jj);
        const uint2 v0 = *(const uint2*)&s_stage[wid][0][jj * 4 + 0][lane * 8];
        const uint2 v1 = *(const uint2*)&s_stage[wid][0][jj * 4 + 1][lane * 8];
        const uint2 v2 = *(const uint2*)&s_stage[wid][0][jj * 4 + 2][lane * 8];
        const uint2 v3 = *(const uint2*)&s_stage[wid][0][jj * 4 + 3][lane * 8];
        fma4u(v0, w4.x, ax, ay, az, aw);
        fma4u(v1, w4.y, ax, ay, az, aw);
        fma4u(v2, w4.z, ax, ay, az, aw);
        fma4u(v3, w4.w, ax, ay, az, aw);
    }

    // ---- Consume chunk 1 ----
    asm volatile("cp.async.wait_group 0;\n");
#pragma unroll
    for (int jj = 0; jj < CHUNK / 4; ++jj) {
        const float4 w4 = __ldg(wp4 + CHUNK / 4 + jj);
        const uint2 v0 = *(const uint2*)&s_stage[wid][1][jj * 4 + 0][lane * 8];
        const uint2 v1 = *(const uint2*)&s_stage[wid][1][jj * 4 + 1][lane * 8];
        const uint2 v2 = *(const uint2*)&s_stage[wid][1][jj * 4 + 2][lane * 8];
        const uint2 v3 = *(const uint2*)&s_stage[wid][1][jj * 4 + 3][lane * 8];
        fma4u(v0, w4.x, ax, ay, az, aw);
        fma4u(v1, w4.y, ax, ay, az, aw);
        fma4u(v2, w4.z, ax, ay, az, aw);
        fma4u(v3, w4.w, ax, ay, az, aw);
    }

    const __half2 r01 = __floats2half2_rn(fast_sigmoid(SCALE * ax),
                                          fast_sigmoid(SCALE * ay));
    const __half2 r23 = __floats2half2_rn(fast_sigmoid(SCALE * az),
                                          fast_sigmoid(SCALE * aw));
    uint2 packed;
    packed.x = *(const unsigned int*)&r01;
    packed.y = *(const unsigned int*)&r23;
    *(uint2*)(g_buf + (size_t)(base + h) * BATCH + lane * 4) = packed;
}

// ---------------------------------------------------------------------------
// Kernel 3: output layer (tiny). One warp per output unit, fp32 accumulation.
// ---------------------------------------------------------------------------
__device__ __forceinline__ float4 gather4(int n, int lane) {
    const uint2 raw = __ldg((const uint2*)(g_buf + (size_t)n * BATCH + lane * 4));
    const float2 f01 = __half22float2(*(const __half2*)&raw.x);
    const float2 f23 = __half22float2(*(const __half2*)&raw.y);
    return make_float4(f01.x, f01.y, f23.x, f23.y);
}

__global__ void __launch_bounds__(BATCH) output_kernel(
    const float* __restrict__ w_out,   // [O, KO]
    const int*   __restrict__ idx_out, // [O, KO]
    float*       __restrict__ out)     // [B, O]
{
    const int lane = threadIdx.x & 31;
    const int wid  = threadIdx.x >> 5;
    const int o    = blockIdx.x * 4 + wid;

    const int4*   ip4 = (const int4*)  (idx_out + (size_t)o * KOUT);
    const float4* wp4 = (const float4*)(w_out   + (size_t)o * KOUT);

    float ax = 0.f, ay = 0.f, az = 0.f, aw = 0.f;

#pragma unroll
    for (int kk = 0; kk < KOUT / 4; ++kk) {
        const int4   i4 = __ldg(ip4 + kk);
        const float4 w4 = __ldg(wp4 + kk);

        const float4 v0 = gather4(i4.x, lane);
        const float4 v1 = gather4(i4.y, lane);
        const float4 v2 = gather4(i4.z, lane);
        const float4 v3 = gather4(i4.w, lane);

        ax = fmaf(w4.x, v0.x, ax); ay = fmaf(w4.x, v0.y, ay);
        az = fmaf(w4.x, v0.z, az); aw = fmaf(w4.x, v0.w, aw);
        ax = fmaf(w4.y, v1.x, ax); ay = fmaf(w4.y, v1.y, ay);
        az = fmaf(w4.y, v1.z, az); aw = fmaf(w4.y, v1.w, aw);
        ax = fmaf(w4.z, v2.x, ax); ay = fmaf(w4.z, v2.y, ay);
        az = fmaf(w4.z, v2.z, az); aw = fmaf(w4.z, v2.w, aw);
        ax = fmaf(w4.w, v3.x, ax); ay = fmaf(w4.w, v3.y, ay);
        az = fmaf(w4.w, v3.z, az); aw = fmaf(w4.w, v3.w, aw);
    }

    const int b0 = lane * 4;
    out[(size_t)(b0 + 0) * NOUT + o] = fast_sigmoid(SCALE * ax);
    out[(size_t)(b0 + 1) * NOUT + o] = fast_sigmoid(SCALE * ay);
    out[(size_t)(b0 + 2) * NOUT + o] = fast_sigmoid(SCALE * az);
    out[(size_t)(b0 + 3) * NOUT + o] = fast_sigmoid(SCALE * aw);
}

// ---------------------------------------------------------------------------
// Launch: 1 init + 8 level + 1 output kernels, all graph-capturable.
// Input order (metadata): x, w_hidden, w_out, idx_hidden, idx_out.
// ---------------------------------------------------------------------------
extern "C" void kernel_launch(void* const* d_in, const int* in_sizes, int n_in,
                              void* d_out, int out_size) {
    const float* x        = (const float*)d_in[0];
    const float* w_hidden = (const float*)d_in[1];  // [L, H, K]
    const float* w_out    = (const float*)d_in[2];  // [O, KO]
    const int*   idx_hid  = (const int*)  d_in[3];  // [L, H, K]
    const int*   idx_out  = (const int*)  d_in[4];  // [O, KO]
    float*       out      = (float*)d_out;          // [B, O]

    init_buf_kernel<<<NUM_IN, BATCH>>>(x);

    for (int l = 0; l < NLEV; ++l) {
        const float* wl = w_hidden + (size_t)l * H * KFAN;
        const int*   il = idx_hid  + (size_t)l * H * KFAN;
        level_kernel<<<H / 4, BATCH>>>(wl, il, NUM_IN + l * H);
    }

    output_kernel<<<NOUT / 4, BATCH>>>(w_out, idx_out, out);
}

// round 14
// speedup vs baseline: 1.5666x; 1.5666x over previous
#include <cuda_runtime.h>
#include <cuda_fp16.h>

#define BATCH   128
#define NUM_IN  4096
#define NLEV    8
#define H       32768
#define KFAN    32
#define NOUT    256
#define KOUT    64
#define SCALE   4.9f

#define NODES   (NUM_IN + NLEV * H)   // 266240 nodes, node-major

// Node-major activation buffer in fp16: buf[node * BATCH + b].  ~65 MB scratch.
__device__ __align__(256) __half g_buf[(size_t)NODES * BATCH];

__device__ __forceinline__ float fast_sigmoid(float x) {
    return 1.0f / (1.0f + __expf(-x));
}

// Gather 4 consecutive batch halves (8B) for node n at batch-quad `lane`.
__device__ __forceinline__ float4 gather4(const __half* __restrict__ buf, int n, int lane) {
    const uint2 raw = __ldg((const uint2*)(buf + (size_t)n * BATCH + lane * 4));
    const __half2 h01 = *(const __half2*)&raw.x;
    const __half2 h23 = *(const __half2*)&raw.y;
    const float2 f01 = __half22float2(h01);
    const float2 f23 = __half22float2(h23);
    return make_float4(f01.x, f01.y, f23.x, f23.y);
}

// ---------------------------------------------------------------------------
// Kernel 1: coalesced transpose+quantize x [B, NUM_IN] -> g_buf (node-major).
// Block covers a 32-node x 128-batch tile via smem; both sides coalesced.
// ---------------------------------------------------------------------------
__global__ void __launch_bounds__(128) init_buf_kernel(const float* __restrict__ x) {
    __shared__ float tile[32][133];   // stride 133: conflict-free
    const int t  = threadIdx.x;
    const int n0 = blockIdx.x * 32;

    const int ni = t & 31;
    const int b4 = t >> 5;
#pragma unroll
    for (int c = 0; c < 32; ++c) {
        const int b = c * 4 + b4;
        tile[ni][b] = __ldg(&x[(size_t)b * NUM_IN + n0 + ni]);
    }
    __syncthreads();

    const int nn = t >> 2;
    const int q  = t & 3;
#pragma unroll
    for (int j = 0; j < 8; ++j) {
        const int b = q * 32 + j * 4;
        const __half2 h01 = __floats2half2_rn(tile[nn][b + 0], tile[nn][b + 1]);
        const __half2 h23 = __floats2half2_rn(tile[nn][b + 2], tile[nn][b + 3]);
        uint2 p;
        p.x = *(const unsigned int*)&h01;
        p.y = *(const unsigned int*)&h23;
        *(uint2*)(g_buf + (size_t)(n0 + nn) * BATCH + b) = p;
    }
}

// ---------------------------------------------------------------------------
// Kernel 2: one topological level.  EXACT R3 champion body — this config
// runs at the measured full-chip LTS byte cap (~6.2 KB/cyc); every variant
// tried (MLP 8, HFMA2, SMEM staging, cp.async, fusion) was equal or worse.
// One warp per hidden unit; each lane owns a batch quad (uint2 = 4 halves,
// 256B coalesced per warp-gather); fp32 convert + FMA accumulation.
// ---------------------------------------------------------------------------
__global__ void __launch_bounds__(BATCH, 8) level_kernel(
    const float* __restrict__ w,    // [H, K] for this level
    const int*   __restrict__ idx,  // [H, K] for this level
    int base)                       // first output node id of this level
{
    const int lane = threadIdx.x & 31;   // batch quad: 4*lane .. 4*lane+3
    const int wid  = threadIdx.x >> 5;
    const int h    = blockIdx.x * 4 + wid;

    const int4*   ip4 = (const int4*)  (idx + (size_t)h * KFAN);
    const float4* wp4 = (const float4*)(w   + (size_t)h * KFAN);

    float ax = 0.f, ay = 0.f, az = 0.f, aw = 0.f;

#pragma unroll
    for (int kk = 0; kk < KFAN / 4; ++kk) {
        const int4   i4 = __ldg(ip4 + kk);   // warp-uniform broadcast
        const float4 w4 = __ldg(wp4 + kk);

        const float4 v0 = gather4(g_buf, i4.x, lane);
        const float4 v1 = gather4(g_buf, i4.y, lane);
        const float4 v2 = gather4(g_buf, i4.z, lane);
        const float4 v3 = gather4(g_buf, i4.w, lane);

        ax = fmaf(w4.x, v0.x, ax); ay = fmaf(w4.x, v0.y, ay);
        az = fmaf(w4.x, v0.z, az); aw = fmaf(w4.x, v0.w, aw);

        ax = fmaf(w4.y, v1.x, ax); ay = fmaf(w4.y, v1.y, ay);
        az = fmaf(w4.y, v1.z, az); aw = fmaf(w4.y, v1.w, aw);

        ax = fmaf(w4.z, v2.x, ax); ay = fmaf(w4.z, v2.y, ay);
        az = fmaf(w4.z, v2.z, az); aw = fmaf(w4.z, v2.w, aw);

        ax = fmaf(w4.w, v3.x, ax); ay = fmaf(w4.w, v3.y, ay);
        az = fmaf(w4.w, v3.z, az); aw = fmaf(w4.w, v3.w, aw);
    }

    const __half2 r01 = __floats2half2_rn(fast_sigmoid(SCALE * ax),
                                          fast_sigmoid(SCALE * ay));
    const __half2 r23 = __floats2half2_rn(fast_sigmoid(SCALE * az),
                                          fast_sigmoid(SCALE * aw));
    uint2 packed;
    packed.x = *(const unsigned int*)&r01;
    packed.y = *(const unsigned int*)&r23;
    *(uint2*)(g_buf + (size_t)(base + h) * BATCH + lane * 4) = packed;
}

// ---------------------------------------------------------------------------
// Kernel 3: output layer (tiny). One warp per output unit, fp32 accumulation.
// ---------------------------------------------------------------------------
__global__ void __launch_bounds__(BATCH) output_kernel(
    const float* __restrict__ w_out,   // [O, KO]
    const int*   __restrict__ idx_out, // [O, KO]
    float*       __restrict__ out)     // [B, O]
{
    const int lane = threadIdx.x & 31;
    const int wid  = threadIdx.x >> 5;
    const int o    = blockIdx.x * 4 + wid;

    const int4*   ip4 = (const int4*)  (idx_out + (size_t)o * KOUT);
    const float4* wp4 = (const float4*)(w_out   + (size_t)o * KOUT);

    float ax = 0.f, ay = 0.f, az = 0.f, aw = 0.f;

#pragma unroll
    for (int kk = 0; kk < KOUT / 4; ++kk) {
        const int4   i4 = __ldg(ip4 + kk);
        const float4 w4 = __ldg(wp4 + kk);

        const float4 v0 = gather4(g_buf, i4.x, lane);
        const float4 v1 = gather4(g_buf, i4.y, lane);
        const float4 v2 = gather4(g_buf, i4.z, lane);
        const float4 v3 = gather4(g_buf, i4.w, lane);

        ax = fmaf(w4.x, v0.x, ax); ay = fmaf(w4.x, v0.y, ay);
        az = fmaf(w4.x, v0.z, az); aw = fmaf(w4.x, v0.w, aw);
        ax = fmaf(w4.y, v1.x, ax); ay = fmaf(w4.y, v1.y, ay);
        az = fmaf(w4.y, v1.z, az); aw = fmaf(w4.y, v1.w, aw);
        ax = fmaf(w4.z, v2.x, ax); ay = fmaf(w4.z, v2.y, ay);
        az = fmaf(w4.z, v2.z, az); aw = fmaf(w4.z, v2.w, aw);
        ax = fmaf(w4.w, v3.x, ax); ay = fmaf(w4.w, v3.y, ay);
        az = fmaf(w4.w, v3.z, az); aw = fmaf(w4.w, v3.w, aw);
    }

    const int b0 = lane * 4;
    out[(size_t)(b0 + 0) * NOUT + o] = fast_sigmoid(SCALE * ax);
    out[(size_t)(b0 + 1) * NOUT + o] = fast_sigmoid(SCALE * ay);
    out[(size_t)(b0 + 2) * NOUT + o] = fast_sigmoid(SCALE * az);
    out[(size_t)(b0 + 3) * NOUT + o] = fast_sigmoid(SCALE * aw);
}

// ---------------------------------------------------------------------------
// Launch: 1 init + 8 level + 1 output kernels, all graph-capturable.
// Input order (metadata): x, w_hidden, w_out, idx_hidden, idx_out.
// ---------------------------------------------------------------------------
extern "C" void kernel_launch(void* const* d_in, const int* in_sizes, int n_in,
                              void* d_out, int out_size) {
    const float* x        = (const float*)d_in[0];
    const float* w_hidden = (const float*)d_in[1];  // [L, H, K]
    const float* w_out    = (const float*)d_in[2];  // [O, KO]
    const int*   idx_hid  = (const int*)  d_in[3];  // [L, H, K]
    const int*   idx_out  = (const int*)  d_in[4];  // [O, KO]
    float*       out      = (float*)d_out;          // [B, O]

    init_buf_kernel<<<NUM_IN / 32, 128>>>(x);

    for (int l = 0; l < NLEV; ++l) {
        const float* wl = w_hidden + (size_t)l * H * KFAN;
        const int*   il = idx_hid  + (size_t)l * H * KFAN;
        level_kernel<<<H / 4, BATCH>>>(wl, il, NUM_IN + l * H);
    }

    output_kernel<<<NOUT / 4, BATCH>>>(w_out, idx_out, out);
}